// round 4
// baseline (speedup 1.0000x reference)
#include <cuda_runtime.h>
#include <math.h>

// CTC loss forward: B=64, T=1000, C=128 (blank=127), L=100, S=201
// One CTA per batch element; one thread per extended-label position.
// NO CTA barrier in the main loop: warps form a skewed pipeline.
//   - intra-warp neighbor alphas via __shfl_up
//   - the single cross-warp value (alpha[32w-1], i.e. lane31 of warp w-1)
//     is published as a packed {step, alpha} 64-bit release-store into a
//     4-deep ring; the consumer acquire-polls it. A consumed-counter
//     provides back-pressure so the producer cannot lap the ring.
// All log-domain math in base 2 via raw MUFU ex2/lg2 approx.

#define Bc 64
#define Tc 1000
#define Cc 128
#define Lc 100
#define Sc 201
#define NW 7
#define NTHREADS 224    // 7 warps

#define NEGV (-1e30f)
#define EPSV (1e-7f)
#define LN2F 0.6931471805599453f

__device__ __forceinline__ float ex2a(float x) {
    float y; asm("ex2.approx.f32 %0, %1;" : "=f"(y) : "f"(x)); return y;
}
__device__ __forceinline__ float lg2a(float x) {
    float y; asm("lg2.approx.f32 %0, %1;" : "=f"(y) : "f"(x)); return y;
}
__device__ __forceinline__ unsigned long long ld_acq64(const unsigned long long* p) {
    unsigned long long v;
    asm volatile("ld.acquire.cta.b64 %0, [%1];" : "=l"(v) : "l"(p) : "memory");
    return v;
}
__device__ __forceinline__ void st_rel64(unsigned long long* p, unsigned long long v) {
    asm volatile("st.release.cta.b64 [%0], %1;" :: "l"(p), "l"(v) : "memory");
}
__device__ __forceinline__ int ld_acq32(const int* p) {
    int v;
    asm volatile("ld.acquire.cta.b32 %0, [%1];" : "=r"(v) : "l"(p) : "memory");
    return v;
}
__device__ __forceinline__ void st_rel32(int* p, int v) {
    asm volatile("st.release.cta.b32 [%0], %1;" :: "l"(p), "r"(v) : "memory");
}

__global__ __launch_bounds__(NTHREADS, 1)
void ctc_loss_kernel(const int* __restrict__ y_true,
                     const float* __restrict__ y_pred,
                     const int* __restrict__ input_len,
                     const int* __restrict__ label_len,
                     float* __restrict__ out)
{
    const int b    = blockIdx.x;
    const int s    = threadIdx.x;         // extended-label position
    const int w    = s >> 5;              // warp id 0..6
    const int lane = s & 31;

    __shared__ unsigned long long ring[NW][4];   // packed {step(hi), alpha_bits(lo)}
    __shared__ int   ccnt[NW];                   // consumer progress (back-pressure)
    __shared__ int   labels[Lc];
    __shared__ float afin[NTHREADS];

    if (s < Lc) labels[s] = y_true[b * Lc + s];
    if (s < NW) ccnt[s] = 0;
    if (s < NW * 4) ring[s >> 2][s & 3] = 0xFFFFFFFF00000000ULL;  // step = -1
    __syncthreads();

    // Per-thread extended label class + skip flag (constant over t).
    int  myclass = Cc - 1;                // blank
    bool skip    = false;
    if (s < Sc && (s & 1)) {
        int j   = (s - 1) >> 1;
        myclass = labels[j];
        skip    = (j >= 1) && (labels[j] != labels[j - 1]);
    }

    int Tb = input_len[b];
    if (Tb > Tc) Tb = Tc;
    const int tmax = Tb - 1;

    const float* col = y_pred + (size_t)b * Tc * Cc + myclass;

    // t = 0 init (base-2 logs)
    float alpha = (s < 2) ? lg2a(col[0] + EPSV) : NEGV;

    // Depth-3 lp pipeline (clamped indices -> unconditional loads).
    float l0 = lg2a(col[(size_t)min(1, tmax) * Cc] + EPSV);
    float l1 = lg2a(col[(size_t)min(2, tmax) * Cc] + EPSV);
    float v  = col[(size_t)min(3, tmax) * Cc];

    // Publish initial boundary state (step 0).
    if (lane == 31)
        ring[w][0] = ((unsigned long long)0u << 32) | __float_as_uint(alpha);
    __syncthreads();   // last CTA barrier before the pipelined loop

    for (int t = 1; t < Tb; ++t) {
        // Intra-warp neighbors.
        float a1 = __shfl_up_sync(0xffffffffu, alpha, 1);
        float a2 = __shfl_up_sync(0xffffffffu, alpha, 2);

        // Cross-warp boundary value (alpha_{t-1}[32w-1]).
        if (w > 0) {
            unsigned long long p;
            do { p = ld_acq64(&ring[w - 1][(t - 1) & 3]); }
            while ((int)(p >> 32) < t - 1);
            float bv = __uint_as_float((unsigned)p);
            if (lane == 0) a1 = bv;
            if (lane == 1) a2 = bv;
            if (lane == 0) st_rel32(&ccnt[w], t);   // slot consumed
        } else {
            if (lane == 0) a1 = NEGV;
        }
        if (!skip) a2 = NEGV;   // covers lane0 (even, never skips) + repeats

        // 3-way log2addexp + lp.
        float lp = l0;
        float m  = fmaxf(alpha, fmaxf(a1, a2));
        float sm = ex2a(alpha - m) + ex2a(a1 - m) + ex2a(a2 - m);
        alpha = m + lg2a(sm) + lp;

        // Back-pressure: don't overwrite slot t&3 (state t-4) until the
        // downstream warp has consumed it (finished its step t-3).
        if (w < NW - 1) {
            while (ld_acq32(&ccnt[w + 1]) < t - 3) {}
        }
        if (lane == 31)
            st_rel64(&ring[w][t & 3],
                     ((unsigned long long)(unsigned)t << 32) | __float_as_uint(alpha));

        // lp pipeline advance (off critical path, after critical MUFUs).
        l0 = l1;
        l1 = lg2a(v + EPSV);
        v  = col[(size_t)min(t + 3, tmax) * Cc];
    }

    // Final gather: loss = -ln2 * log2addexp(alpha[2*ll], alpha[2*ll-1])
    afin[s] = alpha;
    __syncthreads();
    if (s == 0) {
        int   ll = label_len[b];
        float aL = afin[2 * ll];
        float aP = afin[2 * ll - 1];
        float m  = fmaxf(aL, aP);
        out[b] = -LN2F * (m + lg2a(ex2a(aL - m) + ex2a(aP - m)));
    }
}

extern "C" void kernel_launch(void* const* d_in, const int* in_sizes, int n_in,
                              void* d_out, int out_size)
{
    const int*   y_true    = (const int*)  d_in[0];  // [B,L] int32
    const float* y_pred    = (const float*)d_in[1];  // [B,T,C] float32
    const int*   input_len = (const int*)  d_in[2];  // [B] int32
    const int*   label_len = (const int*)  d_in[3];  // [B] int32
    float*       out       = (float*)d_out;          // [B,1] float32

    ctc_loss_kernel<<<Bc, NTHREADS>>>(y_true, y_pred, input_len, label_len, out);
}

// round 7
// speedup vs baseline: 3.0006x; 3.0006x over previous
#include <cuda_runtime.h>
#include <math.h>

// CTC loss forward. Log2-domain alpha storage with LOCALLY-linearized
// 2-step fused updates (no global rescaling -- that was the R5/R6 bug).
// B=64, T=1000, C=128 (blank=127), L=100, S=201.
// One CTA per batch element; one thread per extended-label position.
// Per iteration (2 time steps, one __syncthreads):
//   window w0..w4 = log2-alpha[s-4..s]; m = max5
//   E_i = ex2(w_i - m)                      (5 MUFU)
//   two linear-domain CTC steps with raw probabilities (FMA only)
//   alpha = m + lg2(result)                 (1 MUFU)
// Dropping threshold is 2^-126 relative to the local 5-window max
// (~87 nats; window spread is <= ~2 label transitions) -- same safety
// class as per-step logaddexp.

#define Bc 64
#define Tc 1000
#define Cc 128
#define Lc 100
#define Sc 201
#define NTHREADS 224
#define PAD 8

#define NEGV (-1e30f)
#define EPSV (1e-7f)
#define LN2F 0.6931471805599453f

__device__ __forceinline__ float ex2a(float x) {
    float y; asm("ex2.approx.f32 %0, %1;" : "=f"(y) : "f"(x)); return y;
}
__device__ __forceinline__ float lg2a(float x) {
    float y; asm("lg2.approx.f32 %0, %1;" : "=f"(y) : "f"(x)); return y;
}

__device__ __forceinline__ void pos_info(const int* labels, int p, int& c, float& k) {
    c = Cc - 1; k = 0.f;
    if (p >= 1 && (p & 1)) {
        int j = (p - 1) >> 1;
        if (j > Lc - 1) j = Lc - 1;      // garbage-thread clamp
        c = labels[j];
        if (j >= 1 && labels[j] != labels[j - 1]) k = 1.f;
    }
}

__global__ __launch_bounds__(NTHREADS, 1)
void ctc_loss_kernel(const int* __restrict__ y_true,
                     const float* __restrict__ y_pred,
                     const int* __restrict__ input_len,
                     const int* __restrict__ label_len,
                     float* __restrict__ out)
{
    const int b = blockIdx.x;
    const int s = threadIdx.x;

    __shared__ float abuf_raw[2][PAD + NTHREADS];
    __shared__ int   labels[Lc];

    float* ab0 = &abuf_raw[0][PAD];
    float* ab1 = &abuf_raw[1][PAD];

    if (s < Lc) labels[s] = y_true[b * Lc + s];
    if (s < PAD) { abuf_raw[0][s] = NEGV; abuf_raw[1][s] = NEGV; }
    __syncthreads();

    // Static per-thread info for positions s, s-1, s-2.
    int cls0, cls1, cls2; float sk0, sk1, sk2;
    pos_info(labels, s,     cls0, sk0);
    pos_info(labels, s - 1, cls1, sk1);
    pos_info(labels, s - 2, cls2, sk2);

    int Tb = input_len[b]; if (Tb > Tc) Tb = Tc;
    const int smax = 2 * label_len[b];

    const float* base = y_pred + (size_t)b * Tc * Cc;
    // Column pointers, starting at row 1 (first processed step).
    const float* q0 = base + Cc + cls0;
    const float* q1 = base + Cc + cls1;
    const float* q2 = base + Cc + cls2;

    // t = 0 init: log2-alpha; unreachable positions pinned at NEGV (finite!).
    float alpha = (s < 2) ? lg2a(base[cls0] + EPSV) : NEGV;

    // Prefetch raw probabilities: rows t=1 (3 cols) + row t=2 (cls0).
    float pn0 = q0[0], pn1 = q1[0], pn2 = q2[0], pn3 = q0[Cc];

    int it = 0;
    int t = 1;

    for (; t + 1 < Tb; t += 2, ++it) {
        float pc0 = pn0 + EPSV, pc1 = pn1 + EPSV;
        float pc2 = pn2 + EPSV, pc3 = pn3 + EPSV;

        // Advance to rows t+2 and prefetch next iteration's P values.
        q0 += 2 * Cc; q1 += 2 * Cc; q2 += 2 * Cc;
        if (t + 3 < Tb) { pn0 = q0[0]; pn1 = q1[0]; pn2 = q2[0]; pn3 = q0[Cc]; }

        float* ab = (it & 1) ? ab1 : ab0;
        ab[s] = alpha;
        __syncthreads();
        float w0 = ab[s - 4], w1 = ab[s - 3], w2 = ab[s - 2], w3 = ab[s - 1];

        // Local linearization: window max, then exp2 of all 5 window values.
        float m  = fmaxf(fmaxf(alpha, w3), fmaxf(fmaxf(w2, w1), w0));
        float E4 = ex2a(alpha - m);
        float E3 = ex2a(w3 - m);
        float E2 = ex2a(w2 - m);
        float E1 = ex2a(w1 - m);
        float E0 = ex2a(w0 - m);

        // Step t: positions s, s-1, s-2 (linear domain, redundant recompute).
        float B2 = (E4 + E3 + sk0 * E2) * pc0;
        float B1 = (E3 + E2 + sk1 * E1) * pc1;
        float B0 = (E2 + E1 + sk2 * E0) * pc2;
        // Step t+1: position s.
        float A  = (B2 + B1 + sk0 * B0) * pc3;

        // Back to log2; clamp so dead regions pin at ~NEGV (never -inf/NaN).
        alpha = fmaxf(m + lg2a(A), NEGV);
    }

    // Tail: at most one remaining step (row t via q0/q1-style single step).
    if (t < Tb) {
        float* ab = (it & 1) ? ab1 : ab0;
        ab[s] = alpha;
        __syncthreads();
        float w2 = ab[s - 2], w3 = ab[s - 1];
        float m  = fmaxf(alpha, fmaxf(w3, w2));
        float v  = ex2a(alpha - m) + ex2a(w3 - m) + sk0 * ex2a(w2 - m);
        alpha = fmaxf(m + lg2a(v * (q0[0] + EPSV)), NEGV);
        ++it;
    }

    // Final readout: loss = -ln2 * log2addexp(alpha[smax], alpha[smax-1])
    float* ab = (it & 1) ? ab1 : ab0;
    ab[s] = alpha;
    __syncthreads();
    if (s == 0) {
        float aL = ab[smax];
        float aP = ab[smax - 1];
        float m  = fmaxf(aL, aP);
        out[b] = -LN2F * (m + lg2a(ex2a(aL - m) + ex2a(aP - m)));
    }
}

extern "C" void kernel_launch(void* const* d_in, const int* in_sizes, int n_in,
                              void* d_out, int out_size)
{
    const int*   y_true    = (const int*)  d_in[0];  // [B,L] int32
    const float* y_pred    = (const float*)d_in[1];  // [B,T,C] float32
    const int*   input_len = (const int*)  d_in[2];  // [B] int32
    const int*   label_len = (const int*)  d_in[3];  // [B] int32
    float*       out       = (float*)d_out;          // [B,1] float32

    ctc_loss_kernel<<<Bc, NTHREADS>>>(y_true, y_pred, input_len, label_len, out);
}

// round 8
// speedup vs baseline: 3.1928x; 1.0640x over previous
#include <cuda_runtime.h>
#include <math.h>

// CTC loss forward. Log2-domain alpha storage, locally-linearized 4-step
// fused updates (one __syncthreads per 4 time steps).
// B=64, T=1000, C=128 (blank=127), L=100, S=201.
// One CTA per batch element; one thread per extended-label position.
// Per iteration: window w[0..8] = log2-alpha[s-8..s]; m = max9;
// E = ex2(w - m); 4-layer FMA pyramid (7+5+3+1 redundant position
// updates, raw probabilities); alpha = m + lg2(top).

#define Bc 64
#define Tc 1000
#define Cc 128
#define Lc 100
#define Sc 201
#define NTHREADS 224
#define PAD 8

#define NEGV (-1e30f)
#define EPSV (1e-7f)
#define LN2F 0.6931471805599453f

__device__ __forceinline__ float ex2a(float x) {
    float y; asm("ex2.approx.f32 %0, %1;" : "=f"(y) : "f"(x)); return y;
}
__device__ __forceinline__ float lg2a(float x) {
    float y; asm("lg2.approx.f32 %0, %1;" : "=f"(y) : "f"(x)); return y;
}

__device__ __forceinline__ void pos_info(const int* labels, int p, int& c, float& k) {
    c = Cc - 1; k = 0.f;
    if (p >= 1 && (p & 1)) {
        int j = (p - 1) >> 1;
        if (j > Lc - 1) j = Lc - 1;      // garbage-thread clamp
        c = labels[j];
        if (j >= 1 && labels[j] != labels[j - 1]) k = 1.f;
    }
}

__global__ __launch_bounds__(NTHREADS, 1)
void ctc_loss_kernel(const int* __restrict__ y_true,
                     const float* __restrict__ y_pred,
                     const int* __restrict__ input_len,
                     const int* __restrict__ label_len,
                     float* __restrict__ out)
{
    const int b = blockIdx.x;
    const int s = threadIdx.x;

    __shared__ float abuf_raw[2][PAD + NTHREADS];
    __shared__ int   labels[Lc];

    float* ab0 = &abuf_raw[0][PAD];
    float* ab1 = &abuf_raw[1][PAD];

    if (s < Lc) labels[s] = y_true[b * Lc + s];
    if (s < PAD) { abuf_raw[0][s] = NEGV; abuf_raw[1][s] = NEGV; }
    __syncthreads();

    // Static info for positions s-k, k = 0..6.
    int   cls[7];
    float skf[7];
    #pragma unroll
    for (int k = 0; k < 7; ++k) pos_info(labels, s - k, cls[k], skf[k]);

    int Tb = input_len[b]; if (Tb > Tc) Tb = Tc;
    const int tmax = Tb - 1;
    const int smax = 2 * label_len[b];

    const float* base = y_pred + (size_t)b * Tc * Cc;

    // t = 0 init: log2-alpha; unreachable positions pinned at NEGV (finite).
    float alpha = (s < 2) ? lg2a(base[cls[0]] + EPSV) : NEGV;

    // Prefetch probabilities for the first fused iteration (rows 1..4).
    float pnA[7], pnB[5], pnC[3], pnD;
    {
        const float* R0 = base + (size_t)min(1, tmax) * Cc;
        const float* R1 = base + (size_t)min(2, tmax) * Cc;
        const float* R2 = base + (size_t)min(3, tmax) * Cc;
        const float* R3 = base + (size_t)min(4, tmax) * Cc;
        #pragma unroll
        for (int k = 0; k < 7; ++k) pnA[k] = R0[cls[k]];
        #pragma unroll
        for (int k = 0; k < 5; ++k) pnB[k] = R1[cls[k]];
        #pragma unroll
        for (int k = 0; k < 3; ++k) pnC[k] = R2[cls[k]];
        pnD = R3[cls[0]];
    }

    int it = 0;
    int t = 1;

    for (; t + 3 < Tb; t += 4, ++it) {
        float pcA[7], pcB[5], pcC[3], pcD;
        #pragma unroll
        for (int k = 0; k < 7; ++k) pcA[k] = pnA[k] + EPSV;
        #pragma unroll
        for (int k = 0; k < 5; ++k) pcB[k] = pnB[k] + EPSV;
        #pragma unroll
        for (int k = 0; k < 3; ++k) pcC[k] = pnC[k] + EPSV;
        pcD = pnD + EPSV;

        float* ab = (it & 1) ? ab1 : ab0;
        ab[s] = alpha;
        __syncthreads();

        // Prefetch next iteration's probabilities (rows t+4..t+7, clamped).
        // Issued while the barrier drains (deferred blocking).
        {
            const float* R0 = base + (size_t)min(t + 4, tmax) * Cc;
            const float* R1 = base + (size_t)min(t + 5, tmax) * Cc;
            const float* R2 = base + (size_t)min(t + 6, tmax) * Cc;
            const float* R3 = base + (size_t)min(t + 7, tmax) * Cc;
            #pragma unroll
            for (int k = 0; k < 7; ++k) pnA[k] = R0[cls[k]];
            #pragma unroll
            for (int k = 0; k < 5; ++k) pnB[k] = R1[cls[k]];
            #pragma unroll
            for (int k = 0; k < 3; ++k) pnC[k] = R2[cls[k]];
            pnD = R3[cls[0]];
        }

        // Window read: w[j] = log2-alpha[s-8+j], j = 0..7; w[8] = own alpha.
        float w[8];
        #pragma unroll
        for (int j = 0; j < 8; ++j) w[j] = ab[s - 8 + j];

        float m = alpha;
        #pragma unroll
        for (int j = 0; j < 8; ++j) m = fmaxf(m, w[j]);

        float E[9];
        #pragma unroll
        for (int j = 0; j < 8; ++j) E[j] = ex2a(w[j] - m);
        E[8] = ex2a(alpha - m);

        // Step t: positions s-k, k = 0..6.
        float C1[7];
        #pragma unroll
        for (int k = 0; k < 7; ++k)
            C1[k] = (E[8 - k] + E[7 - k] + skf[k] * E[6 - k]) * pcA[k];
        // Step t+1: k = 0..4.
        float C2[5];
        #pragma unroll
        for (int k = 0; k < 5; ++k)
            C2[k] = (C1[k] + C1[k + 1] + skf[k] * C1[k + 2]) * pcB[k];
        // Step t+2: k = 0..2.
        float C3[3];
        #pragma unroll
        for (int k = 0; k < 3; ++k)
            C3[k] = (C2[k] + C2[k + 1] + skf[k] * C2[k + 2]) * pcC[k];
        // Step t+3: k = 0.
        float A = (C3[0] + C3[1] + skf[0] * C3[2]) * pcD;

        alpha = fmaxf(m + lg2a(A), NEGV);
    }

    // Tail: 0..3 remaining single steps.
    for (; t < Tb; ++t, ++it) {
        float* ab = (it & 1) ? ab1 : ab0;
        ab[s] = alpha;
        __syncthreads();
        float w3 = ab[s - 1], w2 = ab[s - 2];
        float m  = fmaxf(alpha, fmaxf(w3, w2));
        float v  = ex2a(alpha - m) + ex2a(w3 - m) + skf[0] * ex2a(w2 - m);
        float p  = base[(size_t)t * Cc + cls[0]] + EPSV;
        alpha = fmaxf(m + lg2a(v * p), NEGV);
    }

    // Final readout: loss = -ln2 * log2addexp(alpha[smax], alpha[smax-1])
    float* ab = (it & 1) ? ab1 : ab0;
    ab[s] = alpha;
    __syncthreads();
    if (s == 0) {
        float aL = ab[smax];
        float aP = ab[smax - 1];
        float m  = fmaxf(aL, aP);
        out[b] = -LN2F * (m + lg2a(ex2a(aL - m) + ex2a(aP - m)));
    }
}

extern "C" void kernel_launch(void* const* d_in, const int* in_sizes, int n_in,
                              void* d_out, int out_size)
{
    const int*   y_true    = (const int*)  d_in[0];  // [B,L] int32
    const float* y_pred    = (const float*)d_in[1];  // [B,T,C] float32
    const int*   input_len = (const int*)  d_in[2];  // [B] int32
    const int*   label_len = (const int*)  d_in[3];  // [B] int32
    float*       out       = (float*)d_out;          // [B,1] float32

    ctc_loss_kernel<<<Bc, NTHREADS>>>(y_true, y_pred, input_len, label_len, out);
}

// round 9
// speedup vs baseline: 4.6210x; 1.4473x over previous
#include <cuda_runtime.h>
#include <math.h>

// CTC loss forward. Log2-domain alpha, locally-linearized 4-step fused
// updates, TWO positions per thread packed in f32x2 (Blackwell packed FMA).
// B=64, T=1000, C=128 (blank=127), L=100, S=201.
// 128 threads/CTA (4 warps -> exactly 1 warp per SMSP). Thread j owns
// extended positions (2j, 2j+1); position 2j is always blank, 2j+1 is
// labels[j], so pair probabilities are {p_blank, p_label[j]}.
// Per iteration (4 time steps, one __syncthreads):
//   window = 5 float2 pairs (positions 2j-8..2j+1); m = max10
//   E = ex2(w - m); pyramid of 10 packed updates (4+3+2+1), each
//   3 f32x2 ops; alpha = m + lg2(result) per lane.

#define Bc 64
#define Tc 1000
#define Cc 128
#define Lc 100
#define NTHREADS 128
#define NPAIR 128
#define PADP 4

#define NEGV (-1e30f)
#define EPSV (1e-7f)
#define LN2F 0.6931471805599453f

__device__ __forceinline__ float ex2a(float x) {
    float y; asm("ex2.approx.f32 %0, %1;" : "=f"(y) : "f"(x)); return y;
}
__device__ __forceinline__ float lg2a(float x) {
    float y; asm("lg2.approx.f32 %0, %1;" : "=f"(y) : "f"(x)); return y;
}
__device__ __forceinline__ float2 add2(float2 a, float2 b) {
    float2 r;
    asm("{\n\t.reg .b64 A,B,D;\n\t"
        "mov.b64 A,{%2,%3};\n\tmov.b64 B,{%4,%5};\n\t"
        "add.rn.f32x2 D,A,B;\n\t"
        "mov.b64 {%0,%1},D;\n\t}"
        : "=f"(r.x), "=f"(r.y)
        : "f"(a.x), "f"(a.y), "f"(b.x), "f"(b.y));
    return r;
}
__device__ __forceinline__ float2 mul2(float2 a, float2 b) {
    float2 r;
    asm("{\n\t.reg .b64 A,B,D;\n\t"
        "mov.b64 A,{%2,%3};\n\tmov.b64 B,{%4,%5};\n\t"
        "mul.rn.f32x2 D,A,B;\n\t"
        "mov.b64 {%0,%1},D;\n\t}"
        : "=f"(r.x), "=f"(r.y)
        : "f"(a.x), "f"(a.y), "f"(b.x), "f"(b.y));
    return r;
}
__device__ __forceinline__ float2 fma2(float2 a, float2 b, float2 c) {
    float2 r;
    asm("{\n\t.reg .b64 A,B,C,D;\n\t"
        "mov.b64 A,{%2,%3};\n\tmov.b64 B,{%4,%5};\n\tmov.b64 C,{%6,%7};\n\t"
        "fma.rn.f32x2 D,A,B,C;\n\t"
        "mov.b64 {%0,%1},D;\n\t}"
        : "=f"(r.x), "=f"(r.y)
        : "f"(a.x), "f"(a.y), "f"(b.x), "f"(b.y), "f"(c.x), "f"(c.y));
    return r;
}

// One CTC step for pair j: lo = v[2j]+v[2j-1]; hi = v[2j+1]+v[2j]+sk*v[2j-1]
// Q = {v[2j], v[2j+1]}, Qm1 = {v[2j-2], v[2j-1]}, SK = {0, sk}, P = probs.
__device__ __forceinline__ float2 upd(float2 Q, float2 Qm1, float2 SK, float2 P) {
    float2 S1 = make_float2(Qm1.y, Q.x);
    return mul2(fma2(SK, Qm1, add2(Q, S1)), P);
}

__global__ __launch_bounds__(NTHREADS, 1)
void ctc_loss_kernel(const int* __restrict__ y_true,
                     const float* __restrict__ y_pred,
                     const int* __restrict__ input_len,
                     const int* __restrict__ label_len,
                     float* __restrict__ out)
{
    const int b = blockIdx.x;
    const int i = threadIdx.x;                 // pair index

    __shared__ float2 abuf[2][PADP + NPAIR];
    __shared__ int    labels[Lc];

    if (i < Lc) labels[i] = y_true[b * Lc + i];
    if (i < PADP) {
        abuf[0][i] = make_float2(NEGV, NEGV);
        abuf[1][i] = make_float2(NEGV, NEGV);
    }
    __syncthreads();

    // Static per-thread info for pairs i-3..i (odd-position class + skip).
    int    oc[4];
    float2 SK[4];
    #pragma unroll
    for (int k = 0; k < 4; ++k) {
        int pj = i - 3 + k;
        int cj = pj < 0 ? 0 : (pj > Lc - 1 ? Lc - 1 : pj);
        oc[k] = labels[cj];
        int cjm = cj > 0 ? cj - 1 : 0;
        float sk = (pj >= 1 && labels[cj] != labels[cjm]) ? 1.f : 0.f;
        SK[k] = make_float2(0.f, sk);
    }

    int Tb = input_len[b]; if (Tb > Tc) Tb = Tc;
    const int smax = 2 * label_len[b];
    const float* base = y_pred + (size_t)b * Tc * Cc;

    // t = 0 init.
    float2 alpha = (i == 0)
        ? make_float2(lg2a(base[Cc - 1] + EPSV), lg2a(base[oc[3]] + EPSV))
        : make_float2(NEGV, NEGV);

    // Prefetch probability scalars for the first iteration (rows 1..4).
    float bl[4], o0v, o1v[2], o2v[3], o3v[4];
    {
        const float* R = base + Cc;    // row 1 (Tb >= 500, rows 1..4 valid)
        bl[0] = R[Cc - 1]; bl[1] = R[Cc + Cc - 1];
        bl[2] = R[2 * Cc + Cc - 1]; bl[3] = R[3 * Cc + Cc - 1];
        o0v   = R[oc[0]];
        o1v[0] = R[oc[1]]; o1v[1] = R[Cc + oc[1]];
        o2v[0] = R[oc[2]]; o2v[1] = R[Cc + oc[2]]; o2v[2] = R[2 * Cc + oc[2]];
        o3v[0] = R[oc[3]]; o3v[1] = R[Cc + oc[3]];
        o3v[2] = R[2 * Cc + oc[3]]; o3v[3] = R[3 * Cc + oc[3]];
    }

    int it = 0;
    int t = 1;

    for (; t + 3 < Tb; t += 4, ++it) {
        // Pack current probabilities (+eps).
        float b0 = bl[0] + EPSV, b1 = bl[1] + EPSV;
        float b2 = bl[2] + EPSV, b3 = bl[3] + EPSV;
        float2 P1[4] = { make_float2(b0, o0v   + EPSV),
                         make_float2(b0, o1v[0] + EPSV),
                         make_float2(b0, o2v[0] + EPSV),
                         make_float2(b0, o3v[0] + EPSV) };
        float2 P2[3] = { make_float2(b1, o1v[1] + EPSV),
                         make_float2(b1, o2v[1] + EPSV),
                         make_float2(b1, o3v[1] + EPSV) };
        float2 P3[2] = { make_float2(b2, o2v[2] + EPSV),
                         make_float2(b2, o3v[2] + EPSV) };
        float2 P4    =   make_float2(b3, o3v[3] + EPSV);

        float2* ab = abuf[it & 1];
        ab[PADP + i] = alpha;
        __syncthreads();

        // Prefetch next iteration's scalars (rows clamped in-bounds).
        {
            int r0 = t + 4; if (r0 > Tb - 4) r0 = Tb - 4;
            const float* R = base + (size_t)r0 * Cc;
            bl[0] = R[Cc - 1]; bl[1] = R[Cc + Cc - 1];
            bl[2] = R[2 * Cc + Cc - 1]; bl[3] = R[3 * Cc + Cc - 1];
            o0v   = R[oc[0]];
            o1v[0] = R[oc[1]]; o1v[1] = R[Cc + oc[1]];
            o2v[0] = R[oc[2]]; o2v[1] = R[Cc + oc[2]]; o2v[2] = R[2 * Cc + oc[2]];
            o3v[0] = R[oc[3]]; o3v[1] = R[Cc + oc[3]];
            o3v[2] = R[2 * Cc + oc[3]]; o3v[3] = R[3 * Cc + oc[3]];
        }

        // Window: pairs i-4..i-1 from shared, own pair in registers.
        float2 W[4];
        #pragma unroll
        for (int j = 0; j < 4; ++j) W[j] = ab[i + j];   // pair (i-4+j)

        float m = fmaxf(alpha.x, alpha.y);
        #pragma unroll
        for (int j = 0; j < 4; ++j) m = fmaxf(m, fmaxf(W[j].x, W[j].y));

        float2 E[5];
        #pragma unroll
        for (int j = 0; j < 4; ++j)
            E[j] = make_float2(ex2a(W[j].x - m), ex2a(W[j].y - m));
        E[4] = make_float2(ex2a(alpha.x - m), ex2a(alpha.y - m));

        // 4-layer packed pyramid.
        float2 L1[4];
        #pragma unroll
        for (int k = 0; k < 4; ++k) L1[k] = upd(E[k + 1], E[k], SK[k], P1[k]);
        float2 L2[3];
        #pragma unroll
        for (int k = 0; k < 3; ++k) L2[k] = upd(L1[k + 1], L1[k], SK[k + 1], P2[k]);
        float2 L3[2];
        #pragma unroll
        for (int k = 0; k < 2; ++k) L3[k] = upd(L2[k + 1], L2[k], SK[k + 2], P3[k]);
        float2 R4 = upd(L3[1], L3[0], SK[3], P4);

        alpha.x = fmaxf(m + lg2a(R4.x), NEGV);
        alpha.y = fmaxf(m + lg2a(R4.y), NEGV);
    }

    // Tail: 0..3 single steps.
    for (; t < Tb; ++t, ++it) {
        float2* ab = abuf[it & 1];
        ab[PADP + i] = alpha;
        __syncthreads();
        float2 nb = ab[PADP + i - 1];                  // pair i-1
        float pb = base[(size_t)t * Cc + (Cc - 1)] + EPSV;
        float po = base[(size_t)t * Cc + oc[3]]    + EPSV;
        float m  = fmaxf(fmaxf(alpha.x, alpha.y), nb.y);
        float e0 = ex2a(alpha.x - m);
        float e1 = ex2a(alpha.y - m);
        float en = ex2a(nb.y - m);
        float n0 = (e0 + en) * pb;                     // even pos: never skips
        float n1 = (e1 + e0 + SK[3].y * en) * po;
        alpha.x = fmaxf(m + lg2a(n0), NEGV);
        alpha.y = fmaxf(m + lg2a(n1), NEGV);
    }

    // Final readout.
    float2* ab = abuf[it & 1];
    ab[PADP + i] = alpha;
    __syncthreads();
    if (i == 0) {
        const float* af = (const float*)(ab + PADP);
        float aL = af[smax];
        float aP = af[smax - 1];
        float m  = fmaxf(aL, aP);
        out[b] = -LN2F * (m + lg2a(ex2a(aL - m) + ex2a(aP - m)));
    }
}

extern "C" void kernel_launch(void* const* d_in, const int* in_sizes, int n_in,
                              void* d_out, int out_size)
{
    const int*   y_true    = (const int*)  d_in[0];  // [B,L] int32
    const float* y_pred    = (const float*)d_in[1];  // [B,T,C] float32
    const int*   input_len = (const int*)  d_in[2];  // [B] int32
    const int*   label_len = (const int*)  d_in[3];  // [B] int32
    float*       out       = (float*)d_out;          // [B,1] float32

    ctc_loss_kernel<<<Bc, NTHREADS>>>(y_true, y_pred, input_len, label_len, out);
}